// round 15
// baseline (speedup 1.0000x reference)
#include <cuda_runtime.h>
#include <math.h>

#define B_    2
#define S_    2048
#define DIM_  4096
#define NH_   32
#define NKV_  8
#define HD_   128
#define NREP_ 4
#define MTOT  (B_ * S_)   // 4096

// ---------------- scratch (allocation-free: device globals) ----------------
__device__ float g_xq[(size_t)MTOT * NH_ * HD_];   // 64 MB
__device__ float g_xk[(size_t)MTOT * NKV_ * HD_];  // 16 MB
__device__ float g_xv[(size_t)MTOT * NKV_ * HD_];  // 16 MB
__device__ float g_att[(size_t)MTOT * NH_ * HD_];  // 64 MB

// ---------------- SGEMM: C[M,N] = A[M,K] @ B[K,N], all row-major -----------
// 128x128 tile, BK=16, 256 threads, 8x8 per-thread micro-tile.
// Requires M%128==0, N%128==0, K%16==0 (true for all our shapes).
__global__ __launch_bounds__(256)
void sgemm_128x128(const float* __restrict__ A, const float* __restrict__ B,
                   float* __restrict__ C, int M, int N, int K)
{
    __shared__ float As[16][132];   // transposed A tile, padded
    __shared__ float Bs[16][128];

    const int tid = threadIdx.x;
    const int tx = tid & 15;        // 0..15 -> 8 cols each
    const int ty = tid >> 4;        // 0..15 -> 8 rows each
    const int bm = blockIdx.y * 128;
    const int bn = blockIdx.x * 128;

    const float* Ap = A + (size_t)bm * K;
    const float* Bp = B + bn;

    float acc[8][8];
#pragma unroll
    for (int i = 0; i < 8; i++)
#pragma unroll
        for (int j = 0; j < 8; j++) acc[i][j] = 0.f;

    for (int kt = 0; kt < K; kt += 16) {
        // load A tile 128x16 (512 float4), store transposed
#pragma unroll
        for (int it = 0; it < 2; it++) {
            int i = tid + it * 256;
            int r = i >> 2;
            int c = (i & 3) << 2;
            float4 v = *(const float4*)(Ap + (size_t)r * K + kt + c);
            As[c + 0][r] = v.x;
            As[c + 1][r] = v.y;
            As[c + 2][r] = v.z;
            As[c + 3][r] = v.w;
        }
        // load B tile 16x128
#pragma unroll
        for (int it = 0; it < 2; it++) {
            int i = tid + it * 256;
            int r = i >> 5;
            int c = (i & 31) << 2;
            *(float4*)&Bs[r][c] = *(const float4*)(Bp + (size_t)(kt + r) * N + c);
        }
        __syncthreads();

#pragma unroll
        for (int k = 0; k < 16; k++) {
            float4 a0 = *(const float4*)&As[k][ty * 8];
            float4 a1 = *(const float4*)&As[k][ty * 8 + 4];
            float4 b0 = *(const float4*)&Bs[k][tx * 8];
            float4 b1 = *(const float4*)&Bs[k][tx * 8 + 4];
            float a[8] = {a0.x, a0.y, a0.z, a0.w, a1.x, a1.y, a1.z, a1.w};
            float b[8] = {b0.x, b0.y, b0.z, b0.w, b1.x, b1.y, b1.z, b1.w};
#pragma unroll
            for (int i = 0; i < 8; i++)
#pragma unroll
                for (int j = 0; j < 8; j++) acc[i][j] += a[i] * b[j];
        }
        __syncthreads();
    }

#pragma unroll
    for (int i = 0; i < 8; i++) {
        size_t r = (size_t)(bm + ty * 8 + i) * N + bn + tx * 8;
        float4 v0 = make_float4(acc[i][0], acc[i][1], acc[i][2], acc[i][3]);
        float4 v1 = make_float4(acc[i][4], acc[i][5], acc[i][6], acc[i][7]);
        *(float4*)&C[r]     = v0;
        *(float4*)&C[r + 4] = v1;
    }
}

// ---------------- RoPE: in-place on xq [M,NH,HD] and xk [M,NKV,HD] ---------
__global__ __launch_bounds__(256)
void rope_kernel(float* __restrict__ q, float* __restrict__ k,
                 const float* __restrict__ fcos, const float* __restrict__ fsin)
{
    const int QP = MTOT * NH_ * (HD_ / 2);   // 8388608
    const int KP = MTOT * NKV_ * (HD_ / 2);  // 2097152
    int idx = blockIdx.x * blockDim.x + threadIdx.x;
    if (idx < QP) {
        int d2 = idx & 63;
        int rest = idx >> 6;
        int m = rest / NH_;
        int s = m & (S_ - 1);
        float c  = fcos[s * 64 + d2];
        float sn = fsin[s * 64 + d2];
        float2* p = (float2*)q + idx;
        float2 v = *p;
        *p = make_float2(v.x * c - v.y * sn, v.x * sn + v.y * c);
    } else if (idx < QP + KP) {
        int j = idx - QP;
        int d2 = j & 63;
        int rest = j >> 6;
        int m = rest / NKV_;
        int s = m & (S_ - 1);
        float c  = fcos[s * 64 + d2];
        float sn = fsin[s * 64 + d2];
        float2* p = (float2*)k + j;
        float2 v = *p;
        *p = make_float2(v.x * c - v.y * sn, v.x * sn + v.y * c);
    }
}

// ---------------- fused attention (online softmax, no mask) ----------------
// grid: (S/64, NH, B). 256 threads. BQ=64 q rows, BK=64 key rows per tile.
// Thread (tx=tid%16, ty=tid/16): score frag rows ty*4..+3 x cols tx*4..+3,
// O frag rows ty*4..+3 x cols tx*8..+7.
#define SQS 132   // padded stride for 128-wide tiles
#define SPS 68    // padded stride for P tile
#define ATTN_SMEM ((3 * 64 * SQS + 64 * SPS) * 4)   // 118784 bytes

__global__ __launch_bounds__(256)
void attn_kernel(const float* __restrict__ xq, const float* __restrict__ xk,
                 const float* __restrict__ xv, float* __restrict__ out)
{
    extern __shared__ float smem[];
    float* sq = smem;                 // 64 x SQS
    float* sk = sq + 64 * SQS;        // 64 x SQS
    float* sv = sk + 64 * SQS;        // 64 x SQS
    float* sp = sv + 64 * SQS;        // 64 x SPS

    const int tid = threadIdx.x;
    const int tx = tid & 15;
    const int ty = tid >> 4;
    const int qb = blockIdx.x;
    const int h  = blockIdx.y;
    const int b  = blockIdx.z;
    const int kh = h >> 2;            // h / NREP_
    const int q0 = qb * 64;
    const float SCALE = 0.08838834764831845f;  // 1/sqrt(128)

    // load Q tile [64,128]
    for (int i = tid; i < 64 * 32; i += 256) {
        int r  = i >> 5;
        int c4 = (i & 31) << 2;
        size_t g = ((size_t)(b * S_ + q0 + r) * NH_ + h) * HD_ + c4;
        *(float4*)&sq[r * SQS + c4] = *(const float4*)&xq[g];
    }

    float mrow[4], lrow[4], acc[4][8];
#pragma unroll
    for (int i = 0; i < 4; i++) {
        mrow[i] = -INFINITY;
        lrow[i] = 0.f;
#pragma unroll
        for (int c = 0; c < 8; c++) acc[i][c] = 0.f;
    }

    for (int kt = 0; kt < S_ / 64; kt++) {
        __syncthreads();   // also covers Q-tile load on first iteration
        int t0 = kt * 64;
        for (int i = tid; i < 64 * 32; i += 256) {
            int r  = i >> 5;
            int c4 = (i & 31) << 2;
            size_t g = ((size_t)(b * S_ + t0 + r) * NKV_ + kh) * HD_ + c4;
            *(float4*)&sk[r * SQS + c4] = *(const float4*)&xk[g];
            *(float4*)&sv[r * SQS + c4] = *(const float4*)&xv[g];
        }
        __syncthreads();

        // ---- S = Q K^T (4x4 frag) ----
        float sc[4][4];
#pragma unroll
        for (int i = 0; i < 4; i++)
#pragma unroll
            for (int j = 0; j < 4; j++) sc[i][j] = 0.f;

#pragma unroll 8
        for (int kk = 0; kk < HD_; kk += 4) {
            float4 qv[4], kv[4];
#pragma unroll
            for (int i = 0; i < 4; i++)
                qv[i] = *(const float4*)&sq[(ty * 4 + i) * SQS + kk];
#pragma unroll
            for (int j = 0; j < 4; j++)
                kv[j] = *(const float4*)&sk[(tx * 4 + j) * SQS + kk];
#pragma unroll
            for (int i = 0; i < 4; i++)
#pragma unroll
                for (int j = 0; j < 4; j++)
                    sc[i][j] += qv[i].x * kv[j].x + qv[i].y * kv[j].y +
                                qv[i].z * kv[j].z + qv[i].w * kv[j].w;
        }

        // ---- online softmax update ----
#pragma unroll
        for (int i = 0; i < 4; i++) {
#pragma unroll
            for (int j = 0; j < 4; j++) sc[i][j] *= SCALE;
            float mx = fmaxf(fmaxf(sc[i][0], sc[i][1]), fmaxf(sc[i][2], sc[i][3]));
#pragma unroll
            for (int off = 8; off; off >>= 1)
                mx = fmaxf(mx, __shfl_xor_sync(0xffffffffu, mx, off));
            float mnew = fmaxf(mrow[i], mx);
            float corr = __expf(mrow[i] - mnew);
            float rs = 0.f;
#pragma unroll
            for (int j = 0; j < 4; j++) {
                float p = __expf(sc[i][j] - mnew);
                sp[(ty * 4 + i) * SPS + tx * 4 + j] = p;
                rs += p;
            }
#pragma unroll
            for (int off = 8; off; off >>= 1)
                rs += __shfl_xor_sync(0xffffffffu, rs, off);
            lrow[i] = lrow[i] * corr + rs;
            mrow[i] = mnew;
#pragma unroll
            for (int c = 0; c < 8; c++) acc[i][c] *= corr;
        }
        __syncwarp();   // sp producers/consumers share a warp (same ty group)

        // ---- O += P V ----
#pragma unroll 2
        for (int j = 0; j < 64; j += 4) {
            float pq[4][4];
#pragma unroll
            for (int i = 0; i < 4; i++) {
                float4 t = *(const float4*)&sp[(ty * 4 + i) * SPS + j];
                pq[i][0] = t.x; pq[i][1] = t.y; pq[i][2] = t.z; pq[i][3] = t.w;
            }
#pragma unroll
            for (int jj = 0; jj < 4; jj++) {
                float4 va = *(const float4*)&sv[(j + jj) * SQS + tx * 8];
                float4 vb = *(const float4*)&sv[(j + jj) * SQS + tx * 8 + 4];
#pragma unroll
                for (int i = 0; i < 4; i++) {
                    float p = pq[i][jj];
                    acc[i][0] += p * va.x; acc[i][1] += p * va.y;
                    acc[i][2] += p * va.z; acc[i][3] += p * va.w;
                    acc[i][4] += p * vb.x; acc[i][5] += p * vb.y;
                    acc[i][6] += p * vb.z; acc[i][7] += p * vb.w;
                }
            }
        }
    }

    // ---- normalize + write [b, s, NH*HD] ----
#pragma unroll
    for (int i = 0; i < 4; i++) {
        float inv = 1.f / lrow[i];
        size_t g = (size_t)(b * S_ + q0 + ty * 4 + i) * (NH_ * HD_) + h * HD_ + tx * 8;
        float4 v0 = make_float4(acc[i][0] * inv, acc[i][1] * inv,
                                acc[i][2] * inv, acc[i][3] * inv);
        float4 v1 = make_float4(acc[i][4] * inv, acc[i][5] * inv,
                                acc[i][6] * inv, acc[i][7] * inv);
        *(float4*)&out[g]     = v0;
        *(float4*)&out[g + 4] = v1;
    }
}

// ---------------------------------------------------------------------------
extern "C" void kernel_launch(void* const* d_in, const int* in_sizes, int n_in,
                              void* d_out, int out_size)
{
    const float* x    = (const float*)d_in[0];
    const float* wq   = (const float*)d_in[1];
    const float* wk   = (const float*)d_in[2];
    const float* wv   = (const float*)d_in[3];
    const float* wo   = (const float*)d_in[4];
    const float* fcos = (const float*)d_in[5];
    const float* fsin = (const float*)d_in[6];
    // d_in[7], d_in[8] (caches) and d_in[9] (start_pos=0) are not needed.
    float* out = (float*)d_out;

    float *xq, *xk, *xv, *att;
    cudaGetSymbolAddress((void**)&xq,  g_xq);
    cudaGetSymbolAddress((void**)&xk,  g_xk);
    cudaGetSymbolAddress((void**)&xv,  g_xv);
    cudaGetSymbolAddress((void**)&att, g_att);

    cudaFuncSetAttribute(attn_kernel,
                         cudaFuncAttributeMaxDynamicSharedMemorySize, ATTN_SMEM);

    // QKV projections
    sgemm_128x128<<<dim3(DIM_ / 128, MTOT / 128), 256>>>(x, wq, xq, MTOT, NH_ * HD_,  DIM_);
    sgemm_128x128<<<dim3((NKV_ * HD_) / 128, MTOT / 128), 256>>>(x, wk, xk, MTOT, NKV_ * HD_, DIM_);
    sgemm_128x128<<<dim3((NKV_ * HD_) / 128, MTOT / 128), 256>>>(x, wv, xv, MTOT, NKV_ * HD_, DIM_);

    // RoPE on q and k (in place)
    {
        int total = MTOT * NH_ * (HD_ / 2) + MTOT * NKV_ * (HD_ / 2);
        rope_kernel<<<(total + 255) / 256, 256>>>(xq, xk, fcos, fsin);
    }

    // fused attention
    attn_kernel<<<dim3(S_ / 64, NH_, B_), 256, ATTN_SMEM>>>(xq, xk, xv, att);

    // output projection
    sgemm_128x128<<<dim3(DIM_ / 128, MTOT / 128), 256>>>(att, wo, out, MTOT, DIM_, DIM_);
}

// round 16
// speedup vs baseline: 1.6843x; 1.6843x over previous
#include <cuda_runtime.h>
#include <math.h>
#include <stdint.h>

#define B_    2
#define S_    2048
#define DIM_  4096
#define NH_   32
#define NKV_  8
#define HD_   128
#define NREP_ 4
#define MTOT  (B_ * S_)   // 4096

// ---------------- scratch (allocation-free: device globals) ----------------
__device__ float g_xq[(size_t)MTOT * NH_ * HD_];   // 64 MB
__device__ float g_xk[(size_t)MTOT * NKV_ * HD_];  // 16 MB
__device__ float g_xv[(size_t)MTOT * NKV_ * HD_];  // 16 MB
__device__ float g_att[(size_t)MTOT * NH_ * HD_];  // 64 MB

// ---------------- tf32 helpers ----------------------------------------------
__device__ __forceinline__ uint32_t f2tf32(float f) {
    uint32_t u;
    asm("cvt.rna.tf32.f32 %0, %1;" : "=r"(u) : "f"(f));
    return u;
}

#define CP_ASYNC16(dst_u32, src_ptr) \
    asm volatile("cp.async.cg.shared.global [%0], [%1], 16;" :: "r"(dst_u32), "l"(src_ptr))
#define CP_COMMIT() asm volatile("cp.async.commit_group;")
#define CP_WAIT(n)  asm volatile("cp.async.wait_group %0;" :: "n"(n))

// ---------------- tf32 tensor-core GEMM ------------------------------------
// C[M,N] = A[M,K] @ B[K,N], all row-major fp32 in gmem, tf32 mma inside.
// 128x128 tile, BK=32, 256 threads (8 warps as 2(M) x 4(N)), warp tile 64x32,
// mma.sync.m16n8k8, cp.async double-buffered smem.
// Requires M%128==0, N%128==0, K%32==0 (true for all shapes here).
#define AST 36           // A smem stride (floats), 128 rows
#define BST 136          // B smem stride (floats), 32 rows
#define STAGE_F (128*AST + 32*BST)   // 8960 floats / stage
#define GEMM_SMEM (2 * STAGE_F * 4)  // 71680 bytes

__global__ __launch_bounds__(256, 2)
void gemm_tf32(const float* __restrict__ A, const float* __restrict__ B,
               float* __restrict__ C, int M, int N, int K)
{
    extern __shared__ float sm[];
    const int tid  = threadIdx.x;
    const int lane = tid & 31;
    const int wid  = tid >> 5;
    const int wm   = wid & 1;          // 0..1  (M direction, 64 rows each)
    const int wn   = wid >> 1;         // 0..3  (N direction, 32 cols each)
    const int g    = lane >> 2;        // 0..7
    const int t    = lane & 3;         // 0..3
    const int bm   = blockIdx.y * 128;
    const int bn   = blockIdx.x * 128;

    // staging assignment (per thread: 4 x 16B for A, 4 x 16B for B per tile)
    const int ar = tid >> 3;           // A row (0..31), +32 per it
    const int ac = (tid & 7) * 4;      // A col (0,4,...,28)
    const int br = tid >> 5;           // B row (0..7), +8 per it
    const int bc = (tid & 31) * 4;     // B col (0..124)

    const float* Asrc = A + (size_t)(bm + ar) * K + ac;
    const float* Bsrc = B + (size_t)br * N + bn + bc;

    uint32_t smem_u32 = (uint32_t)__cvta_generic_to_shared(sm);
    const uint32_t adst = smem_u32 + (uint32_t)(ar * AST + ac) * 4u;
    const uint32_t bdst = smem_u32 + (uint32_t)(128 * AST + br * BST + bc) * 4u;

    float acc[4][4][4];
#pragma unroll
    for (int mi = 0; mi < 4; mi++)
#pragma unroll
        for (int ni = 0; ni < 4; ni++)
#pragma unroll
            for (int c = 0; c < 4; c++) acc[mi][ni][c] = 0.f;

    const int T = K / 32;

    // prologue: stage 0
#pragma unroll
    for (int it = 0; it < 4; it++) {
        CP_ASYNC16(adst + (uint32_t)(it * 32 * AST) * 4u, Asrc + (size_t)it * 32 * K);
        CP_ASYNC16(bdst + (uint32_t)(it * 8 * BST) * 4u,  Bsrc + (size_t)it * 8 * N);
    }
    CP_COMMIT();

    for (int kt = 0; kt < T; kt++) {
        const int s = kt & 1;
        if (kt + 1 < T) {
            const float* a = Asrc + (size_t)(kt + 1) * 32;
            const float* b = Bsrc + (size_t)(kt + 1) * 32 * N;
            const uint32_t ad = adst + (uint32_t)((s ^ 1) * STAGE_F) * 4u;
            const uint32_t bd = bdst + (uint32_t)((s ^ 1) * STAGE_F) * 4u;
#pragma unroll
            for (int it = 0; it < 4; it++) {
                CP_ASYNC16(ad + (uint32_t)(it * 32 * AST) * 4u, a + (size_t)it * 32 * K);
                CP_ASYNC16(bd + (uint32_t)(it * 8 * BST) * 4u,  b + (size_t)it * 8 * N);
            }
            CP_COMMIT();
            CP_WAIT(1);
        } else {
            CP_WAIT(0);
        }
        __syncthreads();

        const float* sA = sm + s * STAGE_F;
        const float* sB = sA + 128 * AST;

#pragma unroll
        for (int ks = 0; ks < 4; ks++) {
            uint32_t af[4][4], bf[4][2];
#pragma unroll
            for (int mi = 0; mi < 4; mi++) {
                const float* p = sA + (wm * 64 + mi * 16 + g) * AST + ks * 8 + t;
                af[mi][0] = f2tf32(p[0]);
                af[mi][1] = f2tf32(p[8 * AST]);
                af[mi][2] = f2tf32(p[4]);
                af[mi][3] = f2tf32(p[8 * AST + 4]);
            }
#pragma unroll
            for (int ni = 0; ni < 4; ni++) {
                const float* p = sB + (ks * 8 + t) * BST + wn * 32 + ni * 8 + g;
                bf[ni][0] = f2tf32(p[0]);
                bf[ni][1] = f2tf32(p[4 * BST]);
            }
#pragma unroll
            for (int mi = 0; mi < 4; mi++)
#pragma unroll
                for (int ni = 0; ni < 4; ni++) {
                    asm volatile(
                        "mma.sync.aligned.m16n8k8.row.col.f32.tf32.tf32.f32 "
                        "{%0,%1,%2,%3}, {%4,%5,%6,%7}, {%8,%9}, {%0,%1,%2,%3};"
                        : "+f"(acc[mi][ni][0]), "+f"(acc[mi][ni][1]),
                          "+f"(acc[mi][ni][2]), "+f"(acc[mi][ni][3])
                        : "r"(af[mi][0]), "r"(af[mi][1]), "r"(af[mi][2]), "r"(af[mi][3]),
                          "r"(bf[ni][0]), "r"(bf[ni][1]));
                }
        }
        __syncthreads();
    }

    // epilogue
#pragma unroll
    for (int mi = 0; mi < 4; mi++) {
        const int r0 = bm + wm * 64 + mi * 16 + g;
#pragma unroll
        for (int ni = 0; ni < 4; ni++) {
            const int c0 = bn + wn * 32 + ni * 8 + t * 2;
            *(float2*)&C[(size_t)r0 * N + c0] =
                make_float2(acc[mi][ni][0], acc[mi][ni][1]);
            *(float2*)&C[(size_t)(r0 + 8) * N + c0] =
                make_float2(acc[mi][ni][2], acc[mi][ni][3]);
        }
    }
}

// ---------------- RoPE: in-place on xq [M,NH,HD] and xk [M,NKV,HD] ---------
__global__ __launch_bounds__(256)
void rope_kernel(float* __restrict__ q, float* __restrict__ k,
                 const float* __restrict__ fcos, const float* __restrict__ fsin)
{
    const int QP = MTOT * NH_ * (HD_ / 2);   // 8388608
    const int KP = MTOT * NKV_ * (HD_ / 2);  // 2097152
    int idx = blockIdx.x * blockDim.x + threadIdx.x;
    if (idx < QP) {
        int d2 = idx & 63;
        int rest = idx >> 6;
        int m = rest / NH_;
        int s = m & (S_ - 1);
        float c  = fcos[s * 64 + d2];
        float sn = fsin[s * 64 + d2];
        float2* p = (float2*)q + idx;
        float2 v = *p;
        *p = make_float2(v.x * c - v.y * sn, v.x * sn + v.y * c);
    } else if (idx < QP + KP) {
        int j = idx - QP;
        int d2 = j & 63;
        int rest = j >> 6;
        int m = rest / NKV_;
        int s = m & (S_ - 1);
        float c  = fcos[s * 64 + d2];
        float sn = fsin[s * 64 + d2];
        float2* p = (float2*)k + j;
        float2 v = *p;
        *p = make_float2(v.x * c - v.y * sn, v.x * sn + v.y * c);
    }
}

// ---------------- fused attention (online softmax, no mask) ----------------
// grid: (S/64, NH, B). 256 threads. BQ=64 q rows, BK=64 key rows per tile.
#define SQS 132   // padded stride for 128-wide tiles
#define SPS 68    // padded stride for P tile
#define ATTN_SMEM ((3 * 64 * SQS + 64 * SPS) * 4)   // 118784 bytes

__global__ __launch_bounds__(256)
void attn_kernel(const float* __restrict__ xq, const float* __restrict__ xk,
                 const float* __restrict__ xv, float* __restrict__ out)
{
    extern __shared__ float smem[];
    float* sq = smem;                 // 64 x SQS
    float* sk = sq + 64 * SQS;        // 64 x SQS
    float* sv = sk + 64 * SQS;        // 64 x SQS
    float* sp = sv + 64 * SQS;        // 64 x SPS

    const int tid = threadIdx.x;
    const int tx = tid & 15;
    const int ty = tid >> 4;
    const int qb = blockIdx.x;
    const int h  = blockIdx.y;
    const int b  = blockIdx.z;
    const int kh = h >> 2;            // h / NREP_
    const int q0 = qb * 64;
    const float SCALE = 0.08838834764831845f;  // 1/sqrt(128)

    // load Q tile [64,128]
    for (int i = tid; i < 64 * 32; i += 256) {
        int r  = i >> 5;
        int c4 = (i & 31) << 2;
        size_t g = ((size_t)(b * S_ + q0 + r) * NH_ + h) * HD_ + c4;
        *(float4*)&sq[r * SQS + c4] = *(const float4*)&xq[g];
    }

    float mrow[4], lrow[4], acc[4][8];
#pragma unroll
    for (int i = 0; i < 4; i++) {
        mrow[i] = -INFINITY;
        lrow[i] = 0.f;
#pragma unroll
        for (int c = 0; c < 8; c++) acc[i][c] = 0.f;
    }

    for (int kt = 0; kt < S_ / 64; kt++) {
        __syncthreads();   // also covers Q-tile load on first iteration
        int t0 = kt * 64;
        for (int i = tid; i < 64 * 32; i += 256) {
            int r  = i >> 5;
            int c4 = (i & 31) << 2;
            size_t g = ((size_t)(b * S_ + t0 + r) * NKV_ + kh) * HD_ + c4;
            *(float4*)&sk[r * SQS + c4] = *(const float4*)&xk[g];
            *(float4*)&sv[r * SQS + c4] = *(const float4*)&xv[g];
        }
        __syncthreads();

        // ---- S = Q K^T (4x4 frag) ----
        float sc[4][4];
#pragma unroll
        for (int i = 0; i < 4; i++)
#pragma unroll
            for (int j = 0; j < 4; j++) sc[i][j] = 0.f;

#pragma unroll 8
        for (int kk = 0; kk < HD_; kk += 4) {
            float4 qv[4], kv[4];
#pragma unroll
            for (int i = 0; i < 4; i++)
                qv[i] = *(const float4*)&sq[(ty * 4 + i) * SQS + kk];
#pragma unroll
            for (int j = 0; j < 4; j++)
                kv[j] = *(const float4*)&sk[(tx * 4 + j) * SQS + kk];
#pragma unroll
            for (int i = 0; i < 4; i++)
#pragma unroll
                for (int j = 0; j < 4; j++)
                    sc[i][j] += qv[i].x * kv[j].x + qv[i].y * kv[j].y +
                                qv[i].z * kv[j].z + qv[i].w * kv[j].w;
        }

        // ---- online softmax update ----
#pragma unroll
        for (int i = 0; i < 4; i++) {
#pragma unroll
            for (int j = 0; j < 4; j++) sc[i][j] *= SCALE;
            float mx = fmaxf(fmaxf(sc[i][0], sc[i][1]), fmaxf(sc[i][2], sc[i][3]));
#pragma unroll
            for (int off = 8; off; off >>= 1)
                mx = fmaxf(mx, __shfl_xor_sync(0xffffffffu, mx, off));
            float mnew = fmaxf(mrow[i], mx);
            float corr = __expf(mrow[i] - mnew);
            float rs = 0.f;
#pragma unroll
            for (int j = 0; j < 4; j++) {
                float p = __expf(sc[i][j] - mnew);
                sp[(ty * 4 + i) * SPS + tx * 4 + j] = p;
                rs += p;
            }
#pragma unroll
            for (int off = 8; off; off >>= 1)
                rs += __shfl_xor_sync(0xffffffffu, rs, off);
            lrow[i] = lrow[i] * corr + rs;
            mrow[i] = mnew;
#pragma unroll
            for (int c = 0; c < 8; c++) acc[i][c] *= corr;
        }
        __syncwarp();   // sp producers/consumers share a warp (same ty group)

        // ---- O += P V ----
#pragma unroll 2
        for (int j = 0; j < 64; j += 4) {
            float pq[4][4];
#pragma unroll
            for (int i = 0; i < 4; i++) {
                float4 t = *(const float4*)&sp[(ty * 4 + i) * SPS + j];
                pq[i][0] = t.x; pq[i][1] = t.y; pq[i][2] = t.z; pq[i][3] = t.w;
            }
#pragma unroll
            for (int jj = 0; jj < 4; jj++) {
                float4 va = *(const float4*)&sv[(j + jj) * SQS + tx * 8];
                float4 vb = *(const float4*)&sv[(j + jj) * SQS + tx * 8 + 4];
#pragma unroll
                for (int i = 0; i < 4; i++) {
                    float p = pq[i][jj];
                    acc[i][0] += p * va.x; acc[i][1] += p * va.y;
                    acc[i][2] += p * va.z; acc[i][3] += p * va.w;
                    acc[i][4] += p * vb.x; acc[i][5] += p * vb.y;
                    acc[i][6] += p * vb.z; acc[i][7] += p * vb.w;
                }
            }
        }
    }

    // ---- normalize + write [b, s, NH*HD] ----
#pragma unroll
    for (int i = 0; i < 4; i++) {
        float inv = 1.f / lrow[i];
        size_t g = (size_t)(b * S_ + q0 + ty * 4 + i) * (NH_ * HD_) + h * HD_ + tx * 8;
        float4 v0 = make_float4(acc[i][0] * inv, acc[i][1] * inv,
                                acc[i][2] * inv, acc[i][3] * inv);
        float4 v1 = make_float4(acc[i][4] * inv, acc[i][5] * inv,
                                acc[i][6] * inv, acc[i][7] * inv);
        *(float4*)&out[g]     = v0;
        *(float4*)&out[g + 4] = v1;
    }
}

// ---------------------------------------------------------------------------
extern "C" void kernel_launch(void* const* d_in, const int* in_sizes, int n_in,
                              void* d_out, int out_size)
{
    const float* x    = (const float*)d_in[0];
    const float* wq   = (const float*)d_in[1];
    const float* wk   = (const float*)d_in[2];
    const float* wv   = (const float*)d_in[3];
    const float* wo   = (const float*)d_in[4];
    const float* fcos = (const float*)d_in[5];
    const float* fsin = (const float*)d_in[6];
    // d_in[7], d_in[8] (caches) and d_in[9] (start_pos=0) are not needed.
    float* out = (float*)d_out;

    float *xq, *xk, *xv, *att;
    cudaGetSymbolAddress((void**)&xq,  g_xq);
    cudaGetSymbolAddress((void**)&xk,  g_xk);
    cudaGetSymbolAddress((void**)&xv,  g_xv);
    cudaGetSymbolAddress((void**)&att, g_att);

    cudaFuncSetAttribute(attn_kernel,
                         cudaFuncAttributeMaxDynamicSharedMemorySize, ATTN_SMEM);
    cudaFuncSetAttribute(gemm_tf32,
                         cudaFuncAttributeMaxDynamicSharedMemorySize, GEMM_SMEM);

    // QKV projections (tf32 tensor cores)
    gemm_tf32<<<dim3(DIM_ / 128, MTOT / 128), 256, GEMM_SMEM>>>(x, wq, xq, MTOT, NH_ * HD_,  DIM_);
    gemm_tf32<<<dim3((NKV_ * HD_) / 128, MTOT / 128), 256, GEMM_SMEM>>>(x, wk, xk, MTOT, NKV_ * HD_, DIM_);
    gemm_tf32<<<dim3((NKV_ * HD_) / 128, MTOT / 128), 256, GEMM_SMEM>>>(x, wv, xv, MTOT, NKV_ * HD_, DIM_);

    // RoPE on q and k (in place)
    {
        int total = MTOT * NH_ * (HD_ / 2) + MTOT * NKV_ * (HD_ / 2);
        rope_kernel<<<(total + 255) / 256, 256>>>(xq, xk, fcos, fsin);
    }

    // fused attention (fp32)
    attn_kernel<<<dim3(S_ / 64, NH_, B_), 256, ATTN_SMEM>>>(xq, xk, xv, att);

    // output projection (tf32 tensor cores)
    gemm_tf32<<<dim3(DIM_ / 128, MTOT / 128), 256, GEMM_SMEM>>>(att, wo, out, MTOT, DIM_, DIM_);
}